// round 17
// baseline (speedup 1.0000x reference)
#include <cuda_runtime.h>
#include <cuda_bf16.h>
#include <cstdint>

#define NS (1<<20)
#define GRID 148

// ---- device scratch (static, allocation-free) ----
__device__ float g_T0[NS];
__device__ float g_T1[NS];
__device__ float g_A[NS];      // bf16 A panels: hi[NS] | lo[NS]
__device__ float g_Cm[NS];     // bf16 B(Ct) panels: hi[NS] | lo[NS]
__device__ float g_psi[NS];
__device__ float g_R[1024];
__device__ float g_C16[256];
__device__ float g_K[10*4096];
__device__ unsigned g_bar = 0;
__device__ unsigned g_gen = 0;

// ---- packed fp32x2 helpers ----
__device__ __forceinline__ unsigned long long pk2(float x, float y){
    unsigned long long r; asm("mov.b64 %0,{%1,%2};" : "=l"(r) : "f"(x), "f"(y)); return r;
}
__device__ __forceinline__ float2 upk2(unsigned long long v){
    float2 r; asm("mov.b64 {%0,%1},%2;" : "=f"(r.x), "=f"(r.y) : "l"(v)); return r;
}
__device__ __forceinline__ unsigned long long fma2(unsigned long long a,
        unsigned long long b, unsigned long long c){
    unsigned long long d;
    asm("fma.rn.f32x2 %0,%1,%2,%3;" : "=l"(d) : "l"(a), "l"(b), "l"(c));
    return d;
}

__device__ __forceinline__ float peps_el(const float* __restrict__ peps,
                                         int i,int j,int p,int u,int d,int l,int r){
    return peps[(((((i*5+j)*2+p)*4+u)*4+d)*4+l)*4+r];
}

__device__ __forceinline__ unsigned smem_u32(const void* p){
    unsigned a;
    asm("{ .reg .u64 t; cvta.to.shared.u64 t, %1; cvt.u32.u64 %0, t; }" : "=r"(a) : "l"(p));
    return a;
}

__device__ __forceinline__ void cvt4(float4 v, uint2& hp, uint2& lp){
    __nv_bfloat16 h0=__float2bfloat16(v.x), h1=__float2bfloat16(v.y);
    __nv_bfloat16 h2=__float2bfloat16(v.z), h3=__float2bfloat16(v.w);
    __nv_bfloat16 l0=__float2bfloat16(v.x-__bfloat162float(h0));
    __nv_bfloat16 l1=__float2bfloat16(v.y-__bfloat162float(h1));
    __nv_bfloat16 l2=__float2bfloat16(v.z-__bfloat162float(h2));
    __nv_bfloat16 l3=__float2bfloat16(v.w-__bfloat162float(h3));
    hp.x = ((unsigned)__bfloat16_as_ushort(h1)<<16) | (unsigned)__bfloat16_as_ushort(h0);
    hp.y = ((unsigned)__bfloat16_as_ushort(h3)<<16) | (unsigned)__bfloat16_as_ushort(h2);
    lp.x = ((unsigned)__bfloat16_as_ushort(l1)<<16) | (unsigned)__bfloat16_as_ushort(l0);
    lp.y = ((unsigned)__bfloat16_as_ushort(l3)<<16) | (unsigned)__bfloat16_as_ushort(l2);
}

#define LDSM4(R, addr) asm volatile( \
    "ldmatrix.sync.aligned.m8n8.x4.shared.b16 {%0,%1,%2,%3}, [%4];" \
    : "=r"((R)[0]),"=r"((R)[1]),"=r"((R)[2]),"=r"((R)[3]) : "r"(addr))

#define MMA_BF16(acc, a, b0, b1) asm volatile( \
    "mma.sync.aligned.m16n8k16.row.col.f32.bf16.bf16.f32 " \
    "{%0,%1,%2,%3},{%4,%5,%6,%7},{%8,%9},{%0,%1,%2,%3};" \
    : "+f"((acc)[0]),"+f"((acc)[1]),"+f"((acc)[2]),"+f"((acc)[3]) \
    : "r"((a)[0]),"r"((a)[1]),"r"((a)[2]),"r"((a)[3]), "r"(b0),"r"(b1))

#define CP16(dst, src) asm volatile( \
    "cp.async.cg.shared.global [%0], [%1], 16;" :: "r"(dst), "l"(src))
#define CP_COMMIT() asm volatile("cp.async.commit_group;" ::: "memory")
#define CP_WAIT1() asm volatile("cp.async.wait_group 1;" ::: "memory")
#define CP_WAIT0() asm volatile("cp.async.wait_group 0;" ::: "memory")

// ---- software grid barrier (all GRID blocks co-resident: 1 block/SM) ----
__device__ __forceinline__ void gridbar(){
    __syncthreads();
    if (threadIdx.x==0){
        __threadfence();
        unsigned gen = atomicAdd(&g_gen, 0u);
        if (atomicAdd(&g_bar, 1u) == GRID-1u){
            atomicExch(&g_bar, 0u);
            atomicAdd(&g_gen, 1u);
        } else {
            while (atomicAdd(&g_gen, 0u) == gen) __nanosleep(64);
        }
        __threadfence();
    }
    __syncthreads();
}

// ------------- prep: blocks 0..9 compute K_j; block 10 builds R and C16 -------------
__global__ void prep_kernel(const float* __restrict__ peps, const float* __restrict__ gate){
    int t = threadIdx.x;
    if (blockIdx.x < 10){
        int blk = blockIdx.x;
        int pair = blk/5, j = blk%5;
        int L = (j==0)?1:4, R = (j==4)?1:4;
        int nk = 16*L*L*R*R;
        float* Kg = g_K + blk*4096;
        for (int e=t; e<nk; e+=256){
            int tt=e;
            int rb=tt%R; tt/=R; int ra=tt%R; tt/=R;
            int lb=tt%L; tt/=L; int la=tt%L; tt/=L;
            int mid=tt&3; tt>>=2;
            int pb=tt&1; int pa=tt>>1;
            float s=0.f;
            if (pair==0){
                #pragma unroll
                for(int m=0;m<4;m++)
                    s += peps_el(peps,0,j,pa,0,m,la,ra)*peps_el(peps,1,j,pb,m,mid,lb,rb);
            } else {
                #pragma unroll
                for(int m=0;m<4;m++)
                    s += peps_el(peps,2,j,pa,mid,m,la,ra)*peps_el(peps,3,j,pb,m,0,lb,rb);
            }
            Kg[e]=s;
        }
        return;
    }
    __shared__ float g[16];
    __shared__ float A0[1024];
    __shared__ float A1[1024];
    if (t<16) g[t]=gate[t];
    for (int e=t;e<1024;e+=256) A0[e] = ((e>>5)==(e&31)) ? 1.0f : 0.0f;
    __syncthreads();
    #pragma unroll
    for (int k=0;k<4;k++){
        const float* cur = (k&1)? A1 : A0;
        float* nxt       = (k&1)? A0 : A1;
        int hb=4-k, lb=3-k;
        for (int e=t;e<1024;e+=256){
            int rp=e>>5, c=e&31;
            int i1p=(rp>>hb)&1, i2p=(rp>>lb)&1;
            int base = rp & ~((1<<hb)|(1<<lb));
            float acc=0.f;
            #pragma unroll
            for(int i1=0;i1<2;i1++)
            #pragma unroll
            for(int i2=0;i2<2;i2++)
                acc += g[(i1p*2+i2p)*4+(i1*2+i2)] * cur[(base|(i1<<hb)|(i2<<lb))*32 + c];
            nxt[e]=acc;
        }
        __syncthreads();
    }
    for (int e=t;e<1024;e+=256) g_R[e]=A0[e];
    __syncthreads();
    A0[t] = ((t>>4)==(t&15)) ? 1.0f : 0.0f;
    __syncthreads();
    #pragma unroll
    for (int k=0;k<3;k++){
        const float* cur=(k&1)?A1:A0;
        float* nxt      =(k&1)?A0:A1;
        int hb=3-k, lb=2-k;
        int rp=t>>4, c=t&15;
        int i1p=(rp>>hb)&1,i2p=(rp>>lb)&1;
        int base = rp & ~((1<<hb)|(1<<lb));
        float acc=0.f;
        #pragma unroll
        for(int i1=0;i1<2;i1++)
        #pragma unroll
        for(int i2=0;i2<2;i2++)
            acc += g[(i1p*2+i2p)*4+(i1*2+i2)]*cur[(base|(i1<<hb)|(i2<<lb))*16+c];
        __syncthreads();
        nxt[t]=acc;
        __syncthreads();
    }
    g_C16[t]=A1[t];
}

// ------------- fold23 (absorbs kkprep): grid (256, 2) -------------
__global__ __launch_bounds__(256) void fold23_kernel(){
    int t = threadIdx.x;
    int pb = blockIdx.x, pair = blockIdx.y;
    int pd = pb&15, pbb = (pb>>4)&3, pa = pb>>6;
    const float* Kbase = g_K + pair*5*4096;
    __shared__ float K0s[256];
    __shared__ float K1s[4096];
    __shared__ float K2s[256], K3s[256];
    __shared__ float Ts[256*20];
    __shared__ float Ks[256];
    K0s[t] = Kbase[t];
    for (int e=t;e<4096;e+=256) K1s[e]=Kbase[4096+e];
    int kb2 = ((pa>>1)*2+(pbb>>1))*4+(pd>>2);
    int kb3 = ((pa&1)*2+(pbb&1))*4+(pd&3);
    K2s[t] = Kbase[2*4096 + kb2*256 + t];
    K3s[t] = Kbase[3*4096 + kb3*256 + t];
    __syncthreads();
    {
        int abc=t;
        int a2=abc>>6, b2=(abc>>4)&3, c2=abc&15;
        int kb0 = ((a2>>1)*2+(b2>>1))*4 + (c2>>2);
        int kb1 = ((a2&1)*2+(b2&1))*4 + (c2&3);
        #pragma unroll
        for (int r=0;r<16;r++){
            float acc=0.f;
            #pragma unroll
            for (int m=0;m<16;m++) acc += K0s[kb0*16+m]*K1s[(kb1*16+m)*16+r];
            Ts[t*20+r]=acc;
        }
    }
    {
        int l=t>>4, r=t&15;
        float acc=0.f;
        #pragma unroll
        for (int m=0;m<16;m++) acc += K2s[l*16+m]*K3s[m*16+r];
        Ks[t]=acc;
    }
    __syncthreads();
    float* Tout = pair? g_T1 : g_T0;
    int a2=t>>6, b2=(t>>4)&3, c2=t&15;
    float tv[16];
    #pragma unroll
    for (int l=0;l<16;l++) tv[l]=Ts[t*20+l];
    long obase = ((((long)(a2*4+pa)*16 + b2*4+pbb)*256) + c2*16+pd)*16;
    #pragma unroll
    for (int r4=0;r4<4;r4++){
        float4 o; float* po=(float*)&o;
        #pragma unroll
        for (int q=0;q<4;q++){
            int r=r4*4+q;
            float acc=0.f;
            #pragma unroll
            for (int l=0;l<16;l++) acc += tv[l]*Ks[l*16+r];
            po[q]=acc;
        }
        *(float4*)&Tout[obase + r4*4] = o;
    }
}

// ------------- fold4: final column -> bf16 hi/lo panels ; grid (256, 2) -------------
__global__ __launch_bounds__(256) void fold4_kernel(){
    int c = threadIdx.x;
    int a = blockIdx.x >> 4, b = blockIdx.x & 15;
    int pair = blockIdx.y;
    __shared__ float K4s[256];
    K4s[c] = g_K[(pair*5+4)*4096 + c];
    __syncthreads();
    const float* Tin = pair? g_T1 : g_T0;
    const float* tp = &Tin[(((long)(a*16+b)*256)+c)*16];
    float tv[16];
    #pragma unroll
    for (int l4=0;l4<4;l4++){
        float4 v = *(const float4*)&tp[l4*4];
        tv[l4*4+0]=v.x; tv[l4*4+1]=v.y; tv[l4*4+2]=v.z; tv[l4*4+3]=v.w;
    }
    __nv_bfloat16* dH = (__nv_bfloat16*)(pair? g_Cm : g_A);
    __nv_bfloat16* dL = dH + NS;
    #pragma unroll
    for (int p0=0;p0<2;p0++)
    #pragma unroll
    for (int p1=0;p1<2;p1++){
        float4 o; float* po=(float*)&o;
        #pragma unroll
        for (int d1=0;d1<4;d1++){
            int kb=(p0*2+p1)*4+d1;
            float acc=0.f;
            #pragma unroll
            for (int l=0;l<16;l++) acc += tv[l]*K4s[kb*16+l];
            po[d1]=acc;
        }
        uint2 hp, lp;
        cvt4(o, hp, lp);
        long ei;
        if (pair==0)
            ei = (long)a*65536 + (long)b*2048 + c*4 + p0*32768 + p1*1024;
        else
            ei = (long)(a*64 + p0*32 + b*2 + p1)*1024 + c*4;
        *(uint2*)&dH[ei] = hp;
        *(uint2*)&dL[ei] = lp;
    }
}

// ------------- bf16-split HMMA GEMM, cp.async double-buffered; grid (16, 8) -------------
#define GB_AH 0
#define GB_AL 10240
#define GB_BH 20480
#define GB_BL 25600
#define GB_BUF 30720
#define SMEM_GEMM (2*GB_BUF)

__global__ __launch_bounds__(256) void mma_gemm_kernel(float* __restrict__ psi){
    extern __shared__ __align__(16) __nv_bfloat16 smg[];
    unsigned sb = smem_u32(smg);
    int tid = threadIdx.x, lane = tid&31, w = tid>>5;
    int mrow = (w&3)*32, ncol = (w>>2)*32;
    int m0 = blockIdx.y*128, n0 = blockIdx.x*64;
    const __nv_bfloat16* gAh = (const __nv_bfloat16*)g_A;
    const __nv_bfloat16* gAl = gAh + NS;
    const __nv_bfloat16* gBh = (const __nv_bfloat16*)g_Cm;
    const __nv_bfloat16* gBl = gBh + NS;

    float acc[2][4][4];
    #pragma unroll
    for (int i=0;i<2;i++)
      #pragma unroll
      for (int j=0;j<4;j++)
        #pragma unroll
        for (int q=0;q<4;q++) acc[i][j][q]=0.f;

    int rA0 = (tid)>>2,        kqA0 = (tid&3)*8;
    int rA1 = (tid+256)>>2,    kqA1 = (tid&3)*8;
    int rBt = tid>>2,          kqBt = (tid&3)*8;

    int rA = (lane&7) + ((lane>>3)&1)*8;
    int cAsel = ((lane>>4)&1)*8;
    int rB = (lane&7) + ((lane>>4)&1)*8;
    int cBsel = ((lane>>3)&1)*8;

    {
        unsigned b0 = sb;
        CP16(b0 + GB_AH + (unsigned)(rA0*40+kqA0)*2, gAh + (long)(m0+rA0)*1024 + kqA0);
        CP16(b0 + GB_AH + (unsigned)(rA1*40+kqA1)*2, gAh + (long)(m0+rA1)*1024 + kqA1);
        CP16(b0 + GB_AL + (unsigned)(rA0*40+kqA0)*2, gAl + (long)(m0+rA0)*1024 + kqA0);
        CP16(b0 + GB_AL + (unsigned)(rA1*40+kqA1)*2, gAl + (long)(m0+rA1)*1024 + kqA1);
        CP16(b0 + GB_BH + (unsigned)(rBt*40+kqBt)*2, gBh + (long)(n0+rBt)*1024 + kqBt);
        CP16(b0 + GB_BL + (unsigned)(rBt*40+kqBt)*2, gBl + (long)(n0+rBt)*1024 + kqBt);
        CP_COMMIT();
    }

    for (int ch=0; ch<32; ch++){
        if (ch<31){
            unsigned bn = sb + (unsigned)((ch+1)&1)*GB_BUF;
            int ko = (ch+1)*32;
            CP16(bn + GB_AH + (unsigned)(rA0*40+kqA0)*2, gAh + (long)(m0+rA0)*1024 + ko + kqA0);
            CP16(bn + GB_AH + (unsigned)(rA1*40+kqA1)*2, gAh + (long)(m0+rA1)*1024 + ko + kqA1);
            CP16(bn + GB_AL + (unsigned)(rA0*40+kqA0)*2, gAl + (long)(m0+rA0)*1024 + ko + kqA0);
            CP16(bn + GB_AL + (unsigned)(rA1*40+kqA1)*2, gAl + (long)(m0+rA1)*1024 + ko + kqA1);
            CP16(bn + GB_BH + (unsigned)(rBt*40+kqBt)*2, gBh + (long)(n0+rBt)*1024 + ko + kqBt);
            CP16(bn + GB_BL + (unsigned)(rBt*40+kqBt)*2, gBl + (long)(n0+rBt)*1024 + ko + kqBt);
            CP_COMMIT();
            CP_WAIT1();
        } else {
            CP_WAIT0();
        }
        __syncthreads();
        unsigned bc = sb + (unsigned)(ch&1)*GB_BUF;
        unsigned aH = bc + GB_AH, aL = bc + GB_AL;
        unsigned bH = bc + GB_BH, bL = bc + GB_BL;
        #pragma unroll
        for (int ks=0; ks<2; ks++){
            int colA = ks*16 + cAsel;
            int colB = ks*16 + cBsel;
            unsigned ah[2][4], al[2][4];
            #pragma unroll
            for (int mt=0;mt<2;mt++){
                unsigned offs = (unsigned)(((mrow + mt*16 + rA)*40 + colA)*2);
                LDSM4(ah[mt], aH + offs);
                LDSM4(al[mt], aL + offs);
            }
            unsigned bh[2][4], bl[2][4];
            #pragma unroll
            for (int p=0;p<2;p++){
                unsigned offs = (unsigned)(((ncol + p*16 + rB)*40 + colB)*2);
                LDSM4(bh[p], bH + offs);
                LDSM4(bl[p], bL + offs);
            }
            #pragma unroll
            for (int mt=0;mt<2;mt++)
                #pragma unroll
                for (int nt=0;nt<4;nt++){
                    int p = nt>>1, q = (nt&1)*2;
                    MMA_BF16(acc[mt][nt], ah[mt], bh[p][q], bh[p][q+1]);
                    MMA_BF16(acc[mt][nt], ah[mt], bl[p][q], bl[p][q+1]);
                    MMA_BF16(acc[mt][nt], al[mt], bh[p][q], bh[p][q+1]);
                }
        }
        __syncthreads();
    }
    #pragma unroll
    for (int mt=0;mt<2;mt++){
        #pragma unroll
        for (int nt=0;nt<4;nt++){
            int gr = m0 + mrow + mt*16 + (lane>>2);
            int gc = n0 + ncol + nt*8 + (lane&3)*2;
            *(float2*)&psi[(long)gr*1024 + gc] = make_float2(acc[mt][nt][0], acc[mt][nt][1]);
            *(float2*)&psi[(long)(gr+8)*1024 + gc] = make_float2(acc[mt][nt][2], acc[mt][nt][3]);
        }
    }
}

// ================= persistent sweep kernel: 5 x (hhigh, hmode, va, vb) + gather =================
__global__ __launch_bounds__(256) void sweep_kernel(const int* __restrict__ x,
        float* __restrict__ psi, float* __restrict__ out){
    __shared__ __align__(16) char ARENA[46400];
    const int tid = threadIdx.x, lane = tid&31, w = tid>>5;
    const int blk = blockIdx.x;

    for (int sweep=0; sweep<5; sweep++){
        // ---- hhigh: bits [15-19],[10-14]; 128 tasks ----
        {
            float* S   = (float*)ARENA;          // 8 x 1036
            float* Rs  = S + 8288;               // 1024
            float* RsT = Rs + 1024;              // 1024
            for (int e=tid;e<1024;e+=256){
                float v = g_R[e];
                Rs[e]=v;
                RsT[(e&31)*32 + (e>>5)] = v;
            }
            __syncthreads();
            if (blk < 128){
                unsigned lowbase = (unsigned)blk * 8u;
                for (int it=0; it<32; it++){
                    int idx = tid + it*256;
                    int lo = idx & 7, k = idx >> 3;
                    S[lo*1036 + k] = __ldcg(&psi[(unsigned)k*1024u + lowbase + (unsigned)lo]);
                }
                __syncthreads();
                int low = tid & 7, rp = tid >> 3;
                unsigned long long U2[16];
                #pragma unroll
                for (int e=0;e<16;e++) U2[e]=0ull;
                for (int r=0;r<32;r++){
                    float rv = RsT[r*32+rp];
                    unsigned long long rvp = pk2(rv, rv);
                    const ulonglong2* row2 = (const ulonglong2*)&S[low*1036 + r*32];
                    #pragma unroll
                    for (int c2=0;c2<8;c2++){
                        ulonglong2 tp = row2[c2];
                        U2[c2*2+0] = fma2(rvp, tp.x, U2[c2*2+0]);
                        U2[c2*2+1] = fma2(rvp, tp.y, U2[c2*2+1]);
                    }
                }
                float W[32];
                #pragma unroll
                for (int cp=0;cp<32;cp++){
                    const ulonglong2* Rp2 = (const ulonglong2*)&Rs[cp*32];
                    unsigned long long s2 = 0ull;
                    #pragma unroll
                    for (int c2=0;c2<8;c2++){
                        ulonglong2 rr = Rp2[c2];
                        s2 = fma2(rr.x, U2[c2*2+0], s2);
                        s2 = fma2(rr.y, U2[c2*2+1], s2);
                    }
                    float2 f = upk2(s2);
                    W[cp] = f.x + f.y;
                }
                __syncthreads();
                #pragma unroll
                for (int cp=0;cp<32;cp++) S[low*1036 + rp*32+cp] = W[cp];
                __syncthreads();
                for (int it=0; it<32; it++){
                    int idx = tid + it*256;
                    int lo = idx & 7, k = idx >> 3;
                    __stcg(&psi[(unsigned)k*1024u + lowbase + (unsigned)lo], S[lo*1036 + k]);
                }
            }
        }
        gridbar();

        // ---- hmode (HMMA): bits [5-9],[0-4]; 128 block-tasks ----
        {
            __nv_bfloat16* Rh = (__nv_bfloat16*)ARENA;   // 32*40
            __nv_bfloat16* Rl = Rh + 1280;
            __nv_bfloat16* Th = Rl + 1280;               // 8 x 32*40
            __nv_bfloat16* Tl = Th + 10240;
            for (int e=tid;e<1024;e+=256){
                float v = g_R[e];
                __nv_bfloat16 h = __float2bfloat16(v);
                __nv_bfloat16 l = __float2bfloat16(v - __bfloat162float(h));
                Rh[(e>>5)*40 + (e&31)] = h;
                Rl[(e>>5)*40 + (e&31)] = l;
            }
            __syncthreads();
            if (blk < 128){
                int h = blk*8 + w;
                float* tile = psi + (long)h*1024;
                __nv_bfloat16* Thw = Th + w*1280;
                __nv_bfloat16* Tlw = Tl + w*1280;
                #pragma unroll
                for (int q=0;q<8;q++){
                    int idx4 = lane + q*32;
                    int row = idx4>>3, c0 = (idx4&7)*4;
                    float4 v = __ldcg((const float4*)&tile[row*32 + c0]);
                    uint2 hp, lp;
                    cvt4(v, hp, lp);
                    *(uint2*)&Thw[row*40 + c0] = hp;
                    *(uint2*)&Tlw[row*40 + c0] = lp;
                }
                __syncwarp();
                unsigned uRh = smem_u32(Rh), uRl = smem_u32(Rl);
                unsigned uTh = smem_u32(Thw), uTl = smem_u32(Tlw);
                int rA = (lane&7) + ((lane>>3)&1)*8;
                int cAsel = ((lane>>4)&1)*8;
                int rB = (lane&7) + ((lane>>4)&1)*8;
                int cBsel = ((lane>>3)&1)*8;

                float acc[2][4][4];
                #pragma unroll
                for (int i=0;i<2;i++)
                  #pragma unroll
                  for (int j=0;j<4;j++)
                    #pragma unroll
                    for (int q=0;q<4;q++) acc[i][j][q]=0.f;
                #pragma unroll
                for (int ks=0; ks<2; ks++){
                    int colA = ks*16 + cAsel;
                    int colB = ks*16 + cBsel;
                    unsigned ah[2][4], al[2][4];
                    #pragma unroll
                    for (int mt=0;mt<2;mt++){
                        unsigned offs = (unsigned)(((mt*16 + rA)*40 + colA)*2);
                        LDSM4(ah[mt], uTh + offs);
                        LDSM4(al[mt], uTl + offs);
                    }
                    unsigned bh[2][4], bl[2][4];
                    #pragma unroll
                    for (int p=0;p<2;p++){
                        unsigned offs = (unsigned)(((p*16 + rB)*40 + colB)*2);
                        LDSM4(bh[p], uRh + offs);
                        LDSM4(bl[p], uRl + offs);
                    }
                    #pragma unroll
                    for (int mt=0;mt<2;mt++)
                        #pragma unroll
                        for (int nt=0;nt<4;nt++){
                            int p = nt>>1, q = (nt&1)*2;
                            MMA_BF16(acc[mt][nt], ah[mt], bh[p][q], bh[p][q+1]);
                            MMA_BF16(acc[mt][nt], ah[mt], bl[p][q], bl[p][q+1]);
                            MMA_BF16(acc[mt][nt], al[mt], bh[p][q], bh[p][q+1]);
                        }
                }
                __syncwarp();
                #pragma unroll
                for (int mt=0;mt<2;mt++){
                    #pragma unroll
                    for (int nt=0;nt<4;nt++){
                        int i0 = mt*16 + (lane>>2);
                        int l0 = nt*8 + (lane&3)*2;
                        #pragma unroll
                        for (int q=0;q<4;q++){
                            float v = acc[mt][nt][q];
                            int ii = i0 + (q>>1)*8;
                            int ll = l0 + (q&1);
                            __nv_bfloat16 hh = __float2bfloat16(v);
                            __nv_bfloat16 lo = __float2bfloat16(v - __bfloat162float(hh));
                            Thw[ll*40 + ii] = hh;
                            Tlw[ll*40 + ii] = lo;
                        }
                    }
                }
                __syncwarp();
                #pragma unroll
                for (int i=0;i<2;i++)
                  #pragma unroll
                  for (int j=0;j<4;j++)
                    #pragma unroll
                    for (int q=0;q<4;q++) acc[i][j][q]=0.f;
                #pragma unroll
                for (int ks=0; ks<2; ks++){
                    int colA = ks*16 + cAsel;
                    int colB = ks*16 + cBsel;
                    unsigned ah[2][4], al[2][4];
                    #pragma unroll
                    for (int mt=0;mt<2;mt++){
                        unsigned offs = (unsigned)(((mt*16 + rA)*40 + colA)*2);
                        LDSM4(ah[mt], uRh + offs);
                        LDSM4(al[mt], uRl + offs);
                    }
                    unsigned bh[2][4], bl[2][4];
                    #pragma unroll
                    for (int p=0;p<2;p++){
                        unsigned offs = (unsigned)(((p*16 + rB)*40 + colB)*2);
                        LDSM4(bh[p], uTh + offs);
                        LDSM4(bl[p], uTl + offs);
                    }
                    #pragma unroll
                    for (int mt=0;mt<2;mt++)
                        #pragma unroll
                        for (int nt=0;nt<4;nt++){
                            int p = nt>>1, q = (nt&1)*2;
                            MMA_BF16(acc[mt][nt], ah[mt], bh[p][q], bh[p][q+1]);
                            MMA_BF16(acc[mt][nt], ah[mt], bl[p][q], bl[p][q+1]);
                            MMA_BF16(acc[mt][nt], al[mt], bh[p][q], bh[p][q+1]);
                        }
                }
                #pragma unroll
                for (int mt=0;mt<2;mt++){
                    #pragma unroll
                    for (int nt=0;nt<4;nt++){
                        int o0 = mt*16 + (lane>>2);
                        int l0 = nt*8 + (lane&3)*2;
                        __stcg((float2*)&tile[o0*32 + l0],
                               make_float2(acc[mt][nt][0], acc[mt][nt][1]));
                        __stcg((float2*)&tile[(o0+8)*32 + l0],
                               make_float2(acc[mt][nt][2], acc[mt][nt][3]));
                    }
                }
            }
        }
        gridbar();

        // ---- va: columns {0,1,2}; 256 tasks ----
        {
            float* Cs = (float*)ARENA;     // 256
            float* S  = Cs + 256;          // 256*17
            Cs[tid]=g_C16[tid];
            __syncthreads();
            for (int task = blk; task < 256; task += GRID){
                unsigned f = (unsigned)task;
                unsigned base = ((f&3u)<<3) | (((f>>2)&3u)<<8) | (((f>>4)&3u)<<13) | (((f>>6)&3u)<<18);
                #pragma unroll
                for (int it=0; it<16; it++){
                    unsigned e = (unsigned)tid | ((unsigned)it<<8);
                    unsigned off = (e&7u) | (((e>>3)&7u)<<5) | (((e>>6)&7u)<<10) | (((e>>9)&7u)<<15);
                    int a = (e&1)|((e>>2)&2)|((e>>4)&4)|((e>>6)&8);
                    int b = ((e>>1)&1)|((e>>3)&2)|((e>>5)&4)|((e>>7)&8);
                    int c = ((e>>2)&1)|((e>>4)&2)|((e>>6)&4)|((e>>8)&8);
                    S[(b*16+c)*17 + a] = __ldcg(&psi[base + off]);
                }
                __syncthreads();
                {
                    float v[16], o[16];
                    #pragma unroll
                    for (int a=0;a<16;a++) v[a]=S[tid*17+a];
                    #pragma unroll
                    for (int ap=0;ap<16;ap++){
                        float acc=0.f;
                        #pragma unroll
                        for (int a=0;a<16;a++) acc += Cs[ap*16+a]*v[a];
                        o[ap]=acc;
                    }
                    #pragma unroll
                    for (int a=0;a<16;a++) S[tid*17+a]=o[a];
                }
                __syncthreads();
                {
                    int a=tid>>4, c=tid&15;
                    float v[16], o[16];
                    #pragma unroll
                    for (int b=0;b<16;b++) v[b]=S[(b*16+c)*17 + a];
                    #pragma unroll
                    for (int bp=0;bp<16;bp++){
                        float acc=0.f;
                        #pragma unroll
                        for (int b=0;b<16;b++) acc += Cs[bp*16+b]*v[b];
                        o[bp]=acc;
                    }
                    #pragma unroll
                    for (int b=0;b<16;b++) S[(b*16+c)*17 + a]=o[b];
                }
                __syncthreads();
                {
                    int a=tid&15, b=tid>>4;
                    float v[16], o[16];
                    #pragma unroll
                    for (int c=0;c<16;c++) v[c]=S[(b*16+c)*17 + a];
                    #pragma unroll
                    for (int cp=0;cp<16;cp++){
                        float acc=0.f;
                        #pragma unroll
                        for (int c=0;c<16;c++) acc += Cs[cp*16+c]*v[c];
                        o[cp]=acc;
                    }
                    #pragma unroll
                    for (int c=0;c<16;c++) S[(b*16+c)*17 + a]=o[c];
                }
                __syncthreads();
                #pragma unroll
                for (int it=0; it<16; it++){
                    unsigned e = (unsigned)tid | ((unsigned)it<<8);
                    unsigned off = (e&7u) | (((e>>3)&7u)<<5) | (((e>>6)&7u)<<10) | (((e>>9)&7u)<<15);
                    int a = (e&1)|((e>>2)&2)|((e>>4)&4)|((e>>6)&8);
                    int b = ((e>>1)&1)|((e>>3)&2)|((e>>5)&4)|((e>>7)&8);
                    int c = ((e>>2)&1)|((e>>4)&2)|((e>>6)&4)|((e>>8)&8);
                    __stcg(&psi[base + off], S[(b*16+c)*17 + a]);
                }
                __syncthreads();
            }
        }
        gridbar();

        // ---- vb: columns {3,4}; 512 tasks ----
        {
            float* Cs = (float*)ARENA;     // 256
            float* S  = Cs + 256;          // 128*17
            Cs[tid]=g_C16[tid];
            __syncthreads();
            for (int task = blk; task < 512; task += GRID){
                unsigned f = (unsigned)task;
                unsigned base = ((f&7u)<<5) | (((f>>3)&7u)<<10) | (((f>>6)&7u)<<15);
                #pragma unroll
                for (int it=0; it<8; it++){
                    unsigned e = (unsigned)tid | ((unsigned)it<<8);
                    unsigned off = (e&15u) | (((e>>7)&1u)<<4) | (((e>>4)&1u)<<8) | (((e>>8)&1u)<<9)
                                 | (((e>>5)&1u)<<13) | (((e>>9)&1u)<<14) | (((e>>6)&1u)<<18) | (((e>>10)&1u)<<19);
                    int s = e&7;
                    int d = (e>>3)&15;
                    int g = (e>>7)&15;
                    S[(g*8+s)*17 + d] = __ldcg(&psi[base + off]);
                }
                __syncthreads();
                {
                    int fib = tid>>1, ob = (tid&1)*8;
                    float v[16];
                    #pragma unroll
                    for (int d=0;d<16;d++) v[d]=S[fib*17+d];
                    __syncwarp();
                    #pragma unroll
                    for (int oo=0;oo<8;oo++){
                        int o = ob+oo;
                        float acc=0.f;
                        #pragma unroll
                        for (int d=0;d<16;d++) acc += Cs[o*16+d]*v[d];
                        S[fib*17+o]=acc;
                    }
                }
                __syncthreads();
                {
                    int d = tid>>4, s = (tid>>1)&7, half = tid&1;
                    int ob = half*8;
                    float v[16];
                    #pragma unroll
                    for (int g=0;g<16;g++) v[g]=S[(g*8+s)*17 + d];
                    __syncwarp();
                    #pragma unroll
                    for (int oo=0;oo<8;oo++){
                        int go = ob+oo;
                        float acc=0.f;
                        #pragma unroll
                        for (int g=0;g<16;g++) acc += Cs[go*16+g]*v[g];
                        S[(go*8+s)*17 + d]=acc;
                    }
                }
                __syncthreads();
                #pragma unroll
                for (int it=0; it<8; it++){
                    unsigned e = (unsigned)tid | ((unsigned)it<<8);
                    unsigned off = (e&15u) | (((e>>7)&1u)<<4) | (((e>>4)&1u)<<8) | (((e>>8)&1u)<<9)
                                 | (((e>>5)&1u)<<13) | (((e>>9)&1u)<<14) | (((e>>6)&1u)<<18) | (((e>>10)&1u)<<19);
                    int s = e&7;
                    int d = (e>>3)&15;
                    int g = (e>>7)&15;
                    __stcg(&psi[base + off], S[(g*8+s)*17 + d]);
                }
                __syncthreads();
            }
        }
        gridbar();
    }

    // ---- gather ----
    if (blk==0 && tid<64){
        unsigned idx=0;
        #pragma unroll
        for (int j=0;j<20;j++) idx = (idx<<1) | (unsigned)x[tid*20+j];
        out[tid]=__ldcg(&psi[idx]);
    }
}

extern "C" void kernel_launch(void* const* d_in, const int* in_sizes, int n_in,
                              void* d_out, int out_size){
    const int*   x    = (const int*)d_in[0];
    const float* peps = (const float*)d_in[1];
    const float* gate = (const float*)d_in[2];
    float* out = (float*)d_out;

    float *psi;
    cudaGetSymbolAddress((void**)&psi,  g_psi);

    static int smem_set = 0;
    if (!smem_set){
        cudaFuncSetAttribute(mma_gemm_kernel,
                             cudaFuncAttributeMaxDynamicSharedMemorySize, SMEM_GEMM);
        smem_set = 1;
    }

    prep_kernel<<<11,256>>>(peps, gate);
    fold23_kernel<<<dim3(256,2),256>>>();
    fold4_kernel<<<dim3(256,2),256>>>();

    mma_gemm_kernel<<<dim3(16,8),256,SMEM_GEMM>>>(psi);

    sweep_kernel<<<GRID,256>>>(x, psi, out);
}